// round 15
// baseline (speedup 1.0000x reference)
#include <cuda_runtime.h>
#include <cuda_bf16.h>
#include <cuda_fp16.h>
#include <cstdint>

#define EMBED   768
#define NHEADS  12
#define HDIM    64
#define BATCH   8
#define SEQ     1024
#define MTOT    (BATCH * SEQ)

// ---------------------------------------------------------------------------
// Scratch (allocation-free rule: __device__ globals), 16B-aligned for uint4
// ---------------------------------------------------------------------------
__device__ __align__(16) __half g_x16 [(size_t)MTOT * EMBED];
__device__ __align__(16) __half g_K16 [(size_t)MTOT * EMBED];
__device__ __align__(16) __half g_w16 [(size_t)MTOT * EMBED];
__device__ __align__(16) __half g_Wk16[EMBED * EMBED];
__device__ __align__(16) __half g_Wo16[EMBED * EMBED];

// ---------------------------------------------------------------------------
// Helpers
// ---------------------------------------------------------------------------
__device__ __forceinline__ uint32_t cvta_smem(const void* p) {
    uint32_t a;
    asm("{ .reg .u64 t; cvta.to.shared.u64 t, %1; cvt.u32.u64 %0, t; }"
        : "=r"(a) : "l"(p));
    return a;
}
__device__ __forceinline__ uint32_t sw128(uint32_t off) {
    return off ^ ((off >> 3) & 0x70);
}
__device__ __forceinline__ void ldsm4(uint32_t r[4], uint32_t a) {
    asm volatile("ldmatrix.sync.aligned.m8n8.x4.shared.b16 {%0,%1,%2,%3}, [%4];"
                 : "=r"(r[0]), "=r"(r[1]), "=r"(r[2]), "=r"(r[3]) : "r"(a));
}
__device__ __forceinline__ void ldsm4t(uint32_t r[4], uint32_t a) {
    asm volatile("ldmatrix.sync.aligned.m8n8.x4.trans.shared.b16 {%0,%1,%2,%3}, [%4];"
                 : "=r"(r[0]), "=r"(r[1]), "=r"(r[2]), "=r"(r[3]) : "r"(a));
}
__device__ __forceinline__ void mma16816h(float c[4], const uint32_t a[4],
                                          const uint32_t b[2]) {
    asm volatile(
        "mma.sync.aligned.m16n8k16.row.col.f32.f16.f16.f32 "
        "{%0,%1,%2,%3}, {%4,%5,%6,%7}, {%8,%9}, {%0,%1,%2,%3};"
        : "+f"(c[0]), "+f"(c[1]), "+f"(c[2]), "+f"(c[3])
        : "r"(a[0]), "r"(a[1]), "r"(a[2]), "r"(a[3]), "r"(b[0]), "r"(b[1]));
}
__device__ __forceinline__ uint32_t packh2(float lo, float hi) {
    uint32_t r;
    asm("cvt.rn.f16x2.f32 %0, %1, %2;" : "=r"(r) : "f"(hi), "f"(lo));
    return r;
}
__device__ __forceinline__ uint32_t ex2h2(uint32_t x) {
    uint32_t r;
    asm("ex2.approx.f16x2 %0, %1;" : "=r"(r) : "r"(x));
    return r;
}
__device__ __forceinline__ void cp16(uint32_t dst, const void* src) {
    asm volatile("cp.async.cg.shared.global [%0], [%1], 16;"
                 :: "r"(dst), "l"(src) : "memory");
}
__device__ __forceinline__ void cp_commit() {
    asm volatile("cp.async.commit_group;" ::: "memory");
}
template <int N>
__device__ __forceinline__ void cp_wait() {
    asm volatile("cp.async.wait_group %0;" :: "n"(N) : "memory");
}

// ---------------------------------------------------------------------------
// fp32 -> fp16 converts
// ---------------------------------------------------------------------------
__global__ void to_f16(const float4* __restrict__ in,
                       uint32_t* __restrict__ out, int n4) {
    int i = blockIdx.x * blockDim.x + threadIdx.x;
    if (i >= n4) return;
    float4 v = in[i];
    out[2 * i]     = packh2(v.x, v.y);
    out[2 * i + 1] = packh2(v.z, v.w);
}
__global__ void to_f16_2(const float4* __restrict__ a, uint32_t* __restrict__ oa,
                         const float4* __restrict__ b, uint32_t* __restrict__ ob,
                         int n4) {
    int i = blockIdx.x * blockDim.x + threadIdx.x;
    if (i >= n4) return;
    const float4* in  = blockIdx.y ? b : a;
    uint32_t*     out = blockIdx.y ? ob : oa;
    float4 v = in[i];
    out[2 * i]     = packh2(v.x, v.y);
    out[2 * i + 1] = packh2(v.z, v.w);
}

// ---------------------------------------------------------------------------
// Tensor-core GEMM — R14 config, FROZEN.
// 4 warps/CTA, warp tile 32x64, 3-stage cp.async, (128,3).
// ---------------------------------------------------------------------------
#define GSTG   24576
#define NCHUNK (EMBED / 64)

template <int OUT_F16>
__global__ void __launch_bounds__(128, 3) gemm_tc(
    const __half* __restrict__ A, const __half* __restrict__ W,
    const float* __restrict__ bias, float* __restrict__ Cf,
    __half* __restrict__ C16) {
    extern __shared__ __align__(1024) char smb[];
    const int tid = threadIdx.x;
    const int wm = tid >> 5, lane = tid & 31;
    const int g = lane >> 2, q = lane & 3;
    const int sub = lane & 7, sel = lane >> 3;
    const int bm = blockIdx.y * 128, bn = blockIdx.x * 64;
    const uint32_t sb = cvta_smem(smb);

    auto prefetch = [&](int ch, int st) {
        const uint32_t dst = sb + st * GSTG;
        const int k0 = ch * 64;
        #pragma unroll
        for (int p = 0; p < 8; p++) {
            int idx = tid + p * 128;
            int r = idx >> 3, c8 = idx & 7;
            uint32_t off = sw128(r * 128 + c8 * 16);
            cp16(dst + off, A + (size_t)(bm + r) * EMBED + k0 + c8 * 8);
        }
        #pragma unroll
        for (int p = 0; p < 4; p++) {
            int idx = tid + p * 128;
            int r = idx >> 3, c8 = idx & 7;
            uint32_t off = sw128(r * 128 + c8 * 16);
            cp16(dst + 16384 + off, W + (size_t)(bn + r) * EMBED + k0 + c8 * 8);
        }
        cp_commit();
    };

    float c[2][8][4] = {};

    prefetch(0, 0);
    prefetch(1, 1);
    for (int ch = 0; ch < NCHUNK; ch++) {
        if (ch > 0) __syncthreads();
        if (ch + 2 < NCHUNK) prefetch(ch + 2, (ch + 2) % 3);
        if      (ch + 2 < NCHUNK) cp_wait<2>();
        else if (ch + 1 < NCHUNK) cp_wait<1>();
        else                      cp_wait<0>();
        __syncthreads();
        const uint32_t base = sb + (ch % 3) * GSTG;

        #pragma unroll
        for (int ks = 0; ks < 4; ks++) {
            uint32_t ah[2][4];
            #pragma unroll
            for (int mi = 0; mi < 2; mi++) {
                int row = wm * 32 + mi * 16 + sub + (sel & 1) * 8;
                int colb = ks * 32 + (sel >> 1) * 16;
                ldsm4(ah[mi], base + sw128(row * 128 + colb));
            }
            uint32_t bh[4][4];
            #pragma unroll
            for (int nf2 = 0; nf2 < 4; nf2++) {
                int row = nf2 * 16 + sub + (sel >> 1) * 8;
                int colb = ks * 32 + (sel & 1) * 16;
                ldsm4(bh[nf2], base + 16384 + sw128(row * 128 + colb));
            }
            #pragma unroll
            for (int mi = 0; mi < 2; mi++)
                #pragma unroll
                for (int nf = 0; nf < 8; nf++)
                    mma16816h(c[mi][nf], ah[mi], &bh[nf >> 1][(nf & 1) * 2]);
        }
    }

    #pragma unroll
    for (int mi = 0; mi < 2; mi++) {
        int r0 = bm + wm * 32 + mi * 16 + g;
        #pragma unroll
        for (int nf = 0; nf < 8; nf++) {
            int col = bn + nf * 8 + q * 2;
            float b0 = bias[col], b1 = bias[col + 1];
            float v00 = c[mi][nf][0] + b0, v01 = c[mi][nf][1] + b1;
            float v10 = c[mi][nf][2] + b0, v11 = c[mi][nf][3] + b1;
            size_t o0 = (size_t)r0 * EMBED + col;
            size_t o1 = (size_t)(r0 + 8) * EMBED + col;
            if (OUT_F16) {
                *(uint32_t*)(C16 + o0) = packh2(v00, v01);
                *(uint32_t*)(C16 + o1) = packh2(v10, v11);
            } else {
                *(float2*)(Cf + o0) = make_float2(v00, v01);
                *(float2*)(Cf + o1) = make_float2(v10, v11);
            }
        }
    }
}

// ---------------------------------------------------------------------------
// Tensor-core flash attention, R15: 4 warps/CTA, 32 i-rows per warp.
// Per warp per j-tile: QK per m-subtile (monolithic 32-MMA phase, preserving
// R11's ILP), P stashed as packed fp16 (8 regs/subtile); PV phase shares each
// V-fragment (ldsm4t) across BOTH subtiles -> ldsm per unit work -25%.
// Numerics bit-identical to R11/R13/R14 attention.
// ---------------------------------------------------------------------------
#define ASTG   8192
#define NJT    (SEQ / 64)

__global__ void __launch_bounds__(128, 3) attn_tc(
    const int* __restrict__ mask,
    const __half* __restrict__ K16,
    __half* __restrict__ O16) {
    extern __shared__ __align__(1024) char smb[];
    const int tid = threadIdx.x, wid = tid >> 5, lane = tid & 31;
    const int g = lane >> 2, q = lane & 3;
    const int sub = lane & 7, sel = lane >> 3;
    const int bh = blockIdx.y, b = bh / NHEADS, h = bh % NHEADS;
    const int i0 = blockIdx.x * 128;
    const uint32_t sb = cvta_smem(smb);
    const float Cs = 0.052058761f;  // log2(e)/sqrt(768)

    const size_t headoff = (size_t)b * SEQ * EMBED + h * HDIM;

    // ---- stage Q (fp16, 128 rows), lift 2 m-subtile fragments, pre-scale
    #pragma unroll
    for (int p = 0; p < 8; p++) {
        int idx = tid + p * 128;
        int r = idx >> 3, c8 = idx & 7;
        uint32_t off = sw128(r * 128 + c8 * 16);
        *(uint4*)(smb + off) =
            *(const uint4*)(K16 + headoff + (size_t)(i0 + r) * EMBED + c8 * 8);
    }
    __syncthreads();
    uint32_t q16[2][4][4];
    {
        const uint32_t C2 = packh2(Cs, Cs);
        #pragma unroll
        for (int mi = 0; mi < 2; mi++)
            #pragma unroll
            for (int ks = 0; ks < 4; ks++) {
                int row = wid * 32 + mi * 16 + sub + (sel & 1) * 8;
                int colb = ks * 32 + (sel >> 1) * 16;
                ldsm4(q16[mi][ks], sb + sw128(row * 128 + colb));
                #pragma unroll
                for (int i = 0; i < 4; i++)
                    asm("mul.f16x2 %0, %0, %1;" : "+r"(q16[mi][ks][i]) : "r"(C2));
            }
    }
    __syncthreads();

    auto prefetch = [&](int jt, int st) {
        const uint32_t dst = sb + st * ASTG;
        const int j0 = jt * 64;
        #pragma unroll
        for (int p = 0; p < 4; p++) {
            int idx = tid + p * 128;
            int r = idx >> 3, c8 = idx & 7;
            uint32_t off = sw128(r * 128 + c8 * 16);
            cp16(dst + off, K16 + headoff + (size_t)(j0 + r) * EMBED + c8 * 8);
        }
        cp_commit();
    };

    const int mrow = i0 + wid * 32 + g;
    int mv[4];
    #pragma unroll
    for (int i = 0; i < 4; i++) mv[i] = mask[b * SEQ + mrow + i * 8];
    const uint32_t ones2[2] = {0x3C003C00u, 0x3C003C00u};  // f16x2 {1,1}

    float lc[2][4] = {};   // per subtile: lc[mi][0] = row sum g, [2] = g+8
    float o[2][8][4] = {};

    prefetch(0, 0);
    prefetch(1, 1);
    prefetch(2, 2);
    for (int jt = 0; jt < NJT; jt++) {
        if (jt > 0) __syncthreads();
        if (jt + 3 < NJT) prefetch(jt + 3, (jt + 3) & 3);
        if      (jt + 3 < NJT) cp_wait<3>();
        else if (jt + 2 < NJT) cp_wait<2>();
        else if (jt + 1 < NJT) cp_wait<1>();
        else                   cp_wait<0>();
        __syncthreads();
        const uint32_t base = sb + (jt & 3) * ASTG;

        // ---- QK + exp per m-subtile (monolithic 32-MMA phases), P packed
        uint32_t PH[2][4][4];
        #pragma unroll
        for (int mi = 0; mi < 2; mi++) {
            float s[8][4] = {};
            #pragma unroll
            for (int ks = 0; ks < 4; ks++) {
                #pragma unroll
                for (int nf2 = 0; nf2 < 4; nf2++) {
                    uint32_t bhr[4];
                    int row = nf2 * 16 + sub + (sel >> 1) * 8;
                    int colb = ks * 32 + (sel & 1) * 16;
                    ldsm4(bhr, base + sw128(row * 128 + colb));
                    mma16816h(s[nf2 * 2],     q16[mi][ks], &bhr[0]);
                    mma16816h(s[nf2 * 2 + 1], q16[mi][ks], &bhr[2]);
                }
            }
            const int m0 = mv[mi * 2], m1 = mv[mi * 2 + 1];
            #pragma unroll
            for (int kj = 0; kj < 4; kj++) {
                const float* s0 = s[2 * kj];
                const float* s1 = s[2 * kj + 1];
                uint32_t p0 = m0 ? packh2(s0[0], s0[1]) : 0u;
                uint32_t p1 = m1 ? packh2(s0[2], s0[3]) : 0u;
                uint32_t p2 = m0 ? packh2(s1[0], s1[1]) : 0u;
                uint32_t p3 = m1 ? packh2(s1[2], s1[3]) : 0u;
                PH[mi][kj][0] = ex2h2(p0);
                PH[mi][kj][1] = ex2h2(p1);
                PH[mi][kj][2] = ex2h2(p2);
                PH[mi][kj][3] = ex2h2(p3);
            }
            #pragma unroll
            for (int kj = 0; kj < 4; kj++)
                mma16816h(lc[mi], PH[mi][kj], ones2);
        }

        // ---- PV: each V-fragment loaded ONCE, used by both subtiles
        #pragma unroll
        for (int kj = 0; kj < 4; kj++) {
            #pragma unroll
            for (int nd2 = 0; nd2 < 4; nd2++) {
                uint32_t vh[4];
                int row = kj * 16 + sub + (sel & 1) * 8;
                int colb = nd2 * 32 + (sel >> 1) * 16;
                ldsm4t(vh, base + sw128(row * 128 + colb));
                #pragma unroll
                for (int mi = 0; mi < 2; mi++) {
                    mma16816h(o[mi][nd2 * 2],     PH[mi][kj], &vh[0]);
                    mma16816h(o[mi][nd2 * 2 + 1], PH[mi][kj], &vh[2]);
                }
            }
        }
    }

    // ---- epilogue per subtile
    #pragma unroll
    for (int mi = 0; mi < 2; mi++) {
        float inv0 = 1.f / lc[mi][0], inv1 = 1.f / lc[mi][2];
        const size_t r0 = (size_t)(b * SEQ + i0 + wid * 32 + mi * 16 + g);
        #pragma unroll
        for (int nf = 0; nf < 8; nf++) {
            int col = h * HDIM + nf * 8 + q * 2;
            size_t o0 = r0 * EMBED + col, o1 = (r0 + 8) * EMBED + col;
            *(uint32_t*)(O16 + o0) = packh2(o[mi][nf][0] * inv0, o[mi][nf][1] * inv0);
            *(uint32_t*)(O16 + o1) = packh2(o[mi][nf][2] * inv1, o[mi][nf][3] * inv1);
        }
    }
}

// ---------------------------------------------------------------------------
extern "C" void kernel_launch(void* const* d_in, const int* in_sizes, int n_in,
                              void* d_out, int out_size) {
    // Input order: x, attention_mask, Wq, bq, Wk, bk, Wv, bv, Wo, bo
    const float* x    = (const float*)d_in[0];
    const int*   mask = (const int*)  d_in[1];
    const float* Wk   = (const float*)d_in[4];
    const float* bk   = (const float*)d_in[5];
    const float* Wo   = (const float*)d_in[8];
    const float* bo   = (const float*)d_in[9];
    float*       out  = (float*)d_out;

    __half *x16, *K16, *w16, *Wk16, *Wo16;
    cudaGetSymbolAddress((void**)&x16,  g_x16);
    cudaGetSymbolAddress((void**)&K16,  g_K16);
    cudaGetSymbolAddress((void**)&w16,  g_w16);
    cudaGetSymbolAddress((void**)&Wk16, g_Wk16);
    cudaGetSymbolAddress((void**)&Wo16, g_Wo16);

    const int nX4 = MTOT * EMBED / 4;
    const int nW4 = EMBED * EMBED / 4;
    const int gsm  = 3 * GSTG;   // 73728
    const int asm_ = 4 * ASTG;   // 32768

    cudaFuncSetAttribute(gemm_tc<1>,
                         cudaFuncAttributeMaxDynamicSharedMemorySize, gsm);
    cudaFuncSetAttribute(gemm_tc<0>,
                         cudaFuncAttributeMaxDynamicSharedMemorySize, gsm);
    cudaFuncSetAttribute(attn_tc,
                         cudaFuncAttributeMaxDynamicSharedMemorySize, asm_);

    to_f16<<<(nX4 + 255) / 256, 256>>>((const float4*)x, (uint32_t*)x16, nX4);
    to_f16_2<<<dim3((nW4 + 255) / 256, 2), 256>>>(
        (const float4*)Wk, (uint32_t*)Wk16,
        (const float4*)Wo, (uint32_t*)Wo16, nW4);

    // K = x @ Wk^T + bk  -> K16 (fp16)
    gemm_tc<1><<<dim3(EMBED / 64, MTOT / 128), 128, gsm>>>(
        x16, Wk16, bk, nullptr, K16);

    // fused masked self-attention (Q = K = V = K16) -> w16
    attn_tc<<<dim3(SEQ / 128, BATCH * NHEADS), 128, asm_>>>(mask, K16, w16);

    // out = w @ Wo^T + bo  (f32)
    gemm_tc<0><<<dim3(EMBED / 64, MTOT / 128), 128, gsm>>>(
        w16, Wo16, bo, out, nullptr);
}

// round 16
// speedup vs baseline: 1.0579x; 1.0579x over previous
#include <cuda_runtime.h>
#include <cuda_bf16.h>
#include <cuda_fp16.h>
#include <cstdint>

#define EMBED   768
#define NHEADS  12
#define HDIM    64
#define BATCH   8
#define SEQ     1024
#define MTOT    (BATCH * SEQ)

// ---------------------------------------------------------------------------
// Scratch (allocation-free rule: __device__ globals), 16B-aligned for uint4
// ---------------------------------------------------------------------------
__device__ __align__(16) __half g_x16 [(size_t)MTOT * EMBED];
__device__ __align__(16) __half g_K16 [(size_t)MTOT * EMBED];
__device__ __align__(16) __half g_w16 [(size_t)MTOT * EMBED];
__device__ __align__(16) __half g_Wk16[EMBED * EMBED];
__device__ __align__(16) __half g_Wo16[EMBED * EMBED];

// ---------------------------------------------------------------------------
// Helpers
// ---------------------------------------------------------------------------
__device__ __forceinline__ uint32_t cvta_smem(const void* p) {
    uint32_t a;
    asm("{ .reg .u64 t; cvta.to.shared.u64 t, %1; cvt.u32.u64 %0, t; }"
        : "=r"(a) : "l"(p));
    return a;
}
__device__ __forceinline__ uint32_t sw128(uint32_t off) {
    return off ^ ((off >> 3) & 0x70);
}
__device__ __forceinline__ void ldsm4(uint32_t r[4], uint32_t a) {
    asm volatile("ldmatrix.sync.aligned.m8n8.x4.shared.b16 {%0,%1,%2,%3}, [%4];"
                 : "=r"(r[0]), "=r"(r[1]), "=r"(r[2]), "=r"(r[3]) : "r"(a));
}
__device__ __forceinline__ void ldsm4t(uint32_t r[4], uint32_t a) {
    asm volatile("ldmatrix.sync.aligned.m8n8.x4.trans.shared.b16 {%0,%1,%2,%3}, [%4];"
                 : "=r"(r[0]), "=r"(r[1]), "=r"(r[2]), "=r"(r[3]) : "r"(a));
}
__device__ __forceinline__ void mma16816h(float c[4], const uint32_t a[4],
                                          const uint32_t b[2]) {
    asm volatile(
        "mma.sync.aligned.m16n8k16.row.col.f32.f16.f16.f32 "
        "{%0,%1,%2,%3}, {%4,%5,%6,%7}, {%8,%9}, {%0,%1,%2,%3};"
        : "+f"(c[0]), "+f"(c[1]), "+f"(c[2]), "+f"(c[3])
        : "r"(a[0]), "r"(a[1]), "r"(a[2]), "r"(a[3]), "r"(b[0]), "r"(b[1]));
}
__device__ __forceinline__ uint32_t packh2(float lo, float hi) {
    uint32_t r;
    asm("cvt.rn.f16x2.f32 %0, %1, %2;" : "=r"(r) : "f"(hi), "f"(lo));
    return r;
}
__device__ __forceinline__ uint32_t ex2h2(uint32_t x) {
    uint32_t r;
    asm("ex2.approx.f16x2 %0, %1;" : "=r"(r) : "r"(x));
    return r;
}
__device__ __forceinline__ void cp16(uint32_t dst, const void* src) {
    asm volatile("cp.async.cg.shared.global [%0], [%1], 16;"
                 :: "r"(dst), "l"(src) : "memory");
}
__device__ __forceinline__ void cp_commit() {
    asm volatile("cp.async.commit_group;" ::: "memory");
}
template <int N>
__device__ __forceinline__ void cp_wait() {
    asm volatile("cp.async.wait_group %0;" :: "n"(N) : "memory");
}

// ---------------------------------------------------------------------------
// fp32 -> fp16 convert for ALL three tensors in ONE launch (linear range).
// [0, nX4)                 : x   -> x16
// [nX4, nX4+nW4)           : Wk  -> Wk16
// [nX4+nW4, nX4+2*nW4)     : Wo  -> Wo16
// ---------------------------------------------------------------------------
__global__ void to_f16_all(const float4* __restrict__ x,  uint32_t* __restrict__ ox,
                           const float4* __restrict__ wk, uint32_t* __restrict__ owk,
                           const float4* __restrict__ wo, uint32_t* __restrict__ owo,
                           int nX4, int nW4) {
    int i = blockIdx.x * blockDim.x + threadIdx.x;
    const float4* in;
    uint32_t* out;
    int j;
    if (i < nX4)                  { in = x;  out = ox;  j = i; }
    else if (i < nX4 + nW4)       { in = wk; out = owk; j = i - nX4; }
    else if (i < nX4 + 2 * nW4)   { in = wo; out = owo; j = i - nX4 - nW4; }
    else return;
    float4 v = in[j];
    out[2 * j]     = packh2(v.x, v.y);
    out[2 * j + 1] = packh2(v.z, v.w);
}

// ---------------------------------------------------------------------------
// Tensor-core GEMM, fp16 single product.
// R16: (128,4) occupancy with 2-stage cp.async (was (128,3)/3-stage).
// 4 warps/CTA, warp tile 32x64, CTA tile 128x64, k-chunk 64.
// Stage (24576 B): A 16K | W 8K; 2 stages = 49152 B; 4 CTAs/SM = 196 KB smem.
// ---------------------------------------------------------------------------
#define GSTG   24576
#define NCHUNK (EMBED / 64)

template <int OUT_F16>
__global__ void __launch_bounds__(128, 4) gemm_tc(
    const __half* __restrict__ A, const __half* __restrict__ W,
    const float* __restrict__ bias, float* __restrict__ Cf,
    __half* __restrict__ C16) {
    extern __shared__ __align__(1024) char smb[];
    const int tid = threadIdx.x;
    const int wm = tid >> 5, lane = tid & 31;
    const int g = lane >> 2, q = lane & 3;
    const int sub = lane & 7, sel = lane >> 3;
    const int bm = blockIdx.y * 128, bn = blockIdx.x * 64;
    const uint32_t sb = cvta_smem(smb);

    auto prefetch = [&](int ch, int st) {
        const uint32_t dst = sb + st * GSTG;
        const int k0 = ch * 64;
        #pragma unroll
        for (int p = 0; p < 8; p++) {
            int idx = tid + p * 128;
            int r = idx >> 3, c8 = idx & 7;
            uint32_t off = sw128(r * 128 + c8 * 16);
            cp16(dst + off, A + (size_t)(bm + r) * EMBED + k0 + c8 * 8);
        }
        #pragma unroll
        for (int p = 0; p < 4; p++) {
            int idx = tid + p * 128;
            int r = idx >> 3, c8 = idx & 7;
            uint32_t off = sw128(r * 128 + c8 * 16);
            cp16(dst + 16384 + off, W + (size_t)(bn + r) * EMBED + k0 + c8 * 8);
        }
        cp_commit();
    };

    float c[2][8][4] = {};

    prefetch(0, 0);
    for (int ch = 0; ch < NCHUNK; ch++) {
        if (ch > 0) __syncthreads();
        if (ch + 1 < NCHUNK) { prefetch(ch + 1, (ch + 1) & 1); cp_wait<1>(); }
        else                 { cp_wait<0>(); }
        __syncthreads();
        const uint32_t base = sb + (ch & 1) * GSTG;

        #pragma unroll
        for (int ks = 0; ks < 4; ks++) {
            uint32_t ah[2][4];
            #pragma unroll
            for (int mi = 0; mi < 2; mi++) {
                int row = wm * 32 + mi * 16 + sub + (sel & 1) * 8;
                int colb = ks * 32 + (sel >> 1) * 16;
                ldsm4(ah[mi], base + sw128(row * 128 + colb));
            }
            uint32_t bh[4][4];
            #pragma unroll
            for (int nf2 = 0; nf2 < 4; nf2++) {
                int row = nf2 * 16 + sub + (sel >> 1) * 8;
                int colb = ks * 32 + (sel & 1) * 16;
                ldsm4(bh[nf2], base + 16384 + sw128(row * 128 + colb));
            }
            #pragma unroll
            for (int mi = 0; mi < 2; mi++)
                #pragma unroll
                for (int nf = 0; nf < 8; nf++)
                    mma16816h(c[mi][nf], ah[mi], &bh[nf >> 1][(nf & 1) * 2]);
        }
    }

    #pragma unroll
    for (int mi = 0; mi < 2; mi++) {
        int r0 = bm + wm * 32 + mi * 16 + g;
        #pragma unroll
        for (int nf = 0; nf < 8; nf++) {
            int col = bn + nf * 8 + q * 2;
            float b0 = bias[col], b1 = bias[col + 1];
            float v00 = c[mi][nf][0] + b0, v01 = c[mi][nf][1] + b1;
            float v10 = c[mi][nf][2] + b0, v11 = c[mi][nf][3] + b1;
            size_t o0 = (size_t)r0 * EMBED + col;
            size_t o1 = (size_t)(r0 + 8) * EMBED + col;
            if (OUT_F16) {
                *(uint32_t*)(C16 + o0) = packh2(v00, v01);
                *(uint32_t*)(C16 + o1) = packh2(v10, v11);
            } else {
                *(float2*)(Cf + o0) = make_float2(v00, v01);
                *(float2*)(Cf + o1) = make_float2(v10, v11);
            }
        }
    }
}

// ---------------------------------------------------------------------------
// Tensor-core flash attention — R13/R14 structure, FROZEN (74.5 us proven;
// R12 occupancy-up and R15 ldsm-down variants both regressed).
// ---------------------------------------------------------------------------
#define ASTG   8192
#define NJT    (SEQ / 64)

__global__ void __launch_bounds__(256, 2) attn_tc(
    const int* __restrict__ mask,
    const __half* __restrict__ K16,
    __half* __restrict__ O16) {
    extern __shared__ __align__(1024) char smb[];
    const int tid = threadIdx.x, wid = tid >> 5, lane = tid & 31;
    const int g = lane >> 2, q = lane & 3;
    const int sub = lane & 7, sel = lane >> 3;
    const int bh = blockIdx.y, b = bh / NHEADS, h = bh % NHEADS;
    const int i0 = blockIdx.x * 128;
    const uint32_t sb = cvta_smem(smb);
    const float Cs = 0.052058761f;  // log2(e)/sqrt(768)

    const size_t headoff = (size_t)b * SEQ * EMBED + h * HDIM;

    #pragma unroll
    for (int p = 0; p < 4; p++) {
        int idx = tid + p * 256;
        int r = idx >> 3, c8 = idx & 7;
        uint32_t off = sw128(r * 128 + c8 * 16);
        *(uint4*)(smb + off) =
            *(const uint4*)(K16 + headoff + (size_t)(i0 + r) * EMBED + c8 * 8);
    }
    __syncthreads();
    uint32_t q16[4][4];
    {
        const uint32_t C2 = packh2(Cs, Cs);
        #pragma unroll
        for (int ks = 0; ks < 4; ks++) {
            int row = wid * 16 + sub + (sel & 1) * 8;
            int colb = ks * 32 + (sel >> 1) * 16;
            ldsm4(q16[ks], sb + sw128(row * 128 + colb));
            #pragma unroll
            for (int i = 0; i < 4; i++)
                asm("mul.f16x2 %0, %0, %1;" : "+r"(q16[ks][i]) : "r"(C2));
        }
    }
    __syncthreads();

    auto prefetch = [&](int jt, int st) {
        const uint32_t dst = sb + st * ASTG;
        const int j0 = jt * 64;
        #pragma unroll
        for (int p = 0; p < 2; p++) {
            int idx = tid + p * 256;
            int r = idx >> 3, c8 = idx & 7;
            uint32_t off = sw128(r * 128 + c8 * 16);
            cp16(dst + off, K16 + headoff + (size_t)(j0 + r) * EMBED + c8 * 8);
        }
        cp_commit();
    };

    const int mrow = i0 + wid * 16 + g;
    const int mv0 = mask[b * SEQ + mrow];
    const int mv1 = mask[b * SEQ + mrow + 8];
    const uint32_t ones2[2] = {0x3C003C00u, 0x3C003C00u};  // f16x2 {1,1}

    float lc[4] = {};
    float o[8][4] = {};

    prefetch(0, 0);
    prefetch(1, 1);
    prefetch(2, 2);
    for (int jt = 0; jt < NJT; jt++) {
        if (jt > 0) __syncthreads();
        if (jt + 3 < NJT) prefetch(jt + 3, (jt + 3) & 3);
        if      (jt + 3 < NJT) cp_wait<3>();
        else if (jt + 2 < NJT) cp_wait<2>();
        else if (jt + 1 < NJT) cp_wait<1>();
        else                   cp_wait<0>();
        __syncthreads();
        const uint32_t base = sb + (jt & 3) * ASTG;

        float s[8][4] = {};
        #pragma unroll
        for (int ks = 0; ks < 4; ks++) {
            #pragma unroll
            for (int nf2 = 0; nf2 < 4; nf2++) {
                uint32_t bhr[4];
                int row = nf2 * 16 + sub + (sel >> 1) * 8;
                int colb = ks * 32 + (sel & 1) * 16;
                ldsm4(bhr, base + sw128(row * 128 + colb));
                mma16816h(s[nf2 * 2],     q16[ks], &bhr[0]);
                mma16816h(s[nf2 * 2 + 1], q16[ks], &bhr[2]);
            }
        }

        #pragma unroll
        for (int kj = 0; kj < 4; kj++) {
            uint32_t ph[4];
            {
                const float* s0 = s[2 * kj];
                const float* s1 = s[2 * kj + 1];
                ph[0] = mv0 ? packh2(s0[0], s0[1]) : 0u;
                ph[1] = mv1 ? packh2(s0[2], s0[3]) : 0u;
                ph[2] = mv0 ? packh2(s1[0], s1[1]) : 0u;
                ph[3] = mv1 ? packh2(s1[2], s1[3]) : 0u;
                ph[0] = ex2h2(ph[0]);
                ph[1] = ex2h2(ph[1]);
                ph[2] = ex2h2(ph[2]);
                ph[3] = ex2h2(ph[3]);
            }
            mma16816h(lc, ph, ones2);
            #pragma unroll
            for (int nd2 = 0; nd2 < 4; nd2++) {
                uint32_t vh[4];
                int row = kj * 16 + sub + (sel & 1) * 8;
                int colb = nd2 * 32 + (sel >> 1) * 16;
                ldsm4t(vh, base + sw128(row * 128 + colb));
                mma16816h(o[nd2 * 2],     ph, &vh[0]);
                mma16816h(o[nd2 * 2 + 1], ph, &vh[2]);
            }
        }
    }

    float inv0 = 1.f / lc[0], inv1 = 1.f / lc[2];
    const size_t r0 = (size_t)(b * SEQ + i0 + wid * 16 + g);
    #pragma unroll
    for (int nf = 0; nf < 8; nf++) {
        int col = h * HDIM + nf * 8 + q * 2;
        size_t o0 = r0 * EMBED + col, o1 = (r0 + 8) * EMBED + col;
        *(uint32_t*)(O16 + o0) = packh2(o[nf][0] * inv0, o[nf][1] * inv0);
        *(uint32_t*)(O16 + o1) = packh2(o[nf][2] * inv1, o[nf][3] * inv1);
    }
}

// ---------------------------------------------------------------------------
extern "C" void kernel_launch(void* const* d_in, const int* in_sizes, int n_in,
                              void* d_out, int out_size) {
    // Input order: x, attention_mask, Wq, bq, Wk, bk, Wv, bv, Wo, bo
    const float* x    = (const float*)d_in[0];
    const int*   mask = (const int*)  d_in[1];
    const float* Wk   = (const float*)d_in[4];
    const float* bk   = (const float*)d_in[5];
    const float* Wo   = (const float*)d_in[8];
    const float* bo   = (const float*)d_in[9];
    float*       out  = (float*)d_out;

    __half *x16, *K16, *w16, *Wk16, *Wo16;
    cudaGetSymbolAddress((void**)&x16,  g_x16);
    cudaGetSymbolAddress((void**)&K16,  g_K16);
    cudaGetSymbolAddress((void**)&w16,  g_w16);
    cudaGetSymbolAddress((void**)&Wk16, g_Wk16);
    cudaGetSymbolAddress((void**)&Wo16, g_Wo16);

    const int nX4 = MTOT * EMBED / 4;
    const int nW4 = EMBED * EMBED / 4;
    const int gsm  = 2 * GSTG;   // 49152
    const int asm_ = 4 * ASTG;   // 32768

    cudaFuncSetAttribute(gemm_tc<1>,
                         cudaFuncAttributeMaxDynamicSharedMemorySize, gsm);
    cudaFuncSetAttribute(gemm_tc<0>,
                         cudaFuncAttributeMaxDynamicSharedMemorySize, gsm);
    cudaFuncSetAttribute(attn_tc,
                         cudaFuncAttributeMaxDynamicSharedMemorySize, asm_);

    // one launch: x, Wk, Wo -> fp16
    const int ntot = nX4 + 2 * nW4;
    to_f16_all<<<(ntot + 255) / 256, 256>>>(
        (const float4*)x,  (uint32_t*)x16,
        (const float4*)Wk, (uint32_t*)Wk16,
        (const float4*)Wo, (uint32_t*)Wo16, nX4, nW4);

    // K = x @ Wk^T + bk  -> K16 (fp16)
    gemm_tc<1><<<dim3(EMBED / 64, MTOT / 128), 128, gsm>>>(
        x16, Wk16, bk, nullptr, K16);

    // fused masked self-attention (Q = K = V = K16) -> w16
    attn_tc<<<dim3(SEQ / 128, BATCH * NHEADS), 256, asm_>>>(mask, K16, w16);

    // out = w @ Wo^T + bo  (f32)
    gemm_tc<0><<<dim3(EMBED / 64, MTOT / 128), 128, gsm>>>(
        w16, Wo16, bo, out, nullptr);
}

// round 17
// speedup vs baseline: 1.0673x; 1.0089x over previous
#include <cuda_runtime.h>
#include <cuda_bf16.h>
#include <cuda_fp16.h>
#include <cstdint>

#define EMBED   768
#define NHEADS  12
#define HDIM    64
#define BATCH   8
#define SEQ     1024
#define MTOT    (BATCH * SEQ)

// ---------------------------------------------------------------------------
// Scratch (allocation-free rule: __device__ globals), 16B-aligned for uint4
// ---------------------------------------------------------------------------
__device__ __align__(16) __half g_x16 [(size_t)MTOT * EMBED];
__device__ __align__(16) __half g_K16 [(size_t)MTOT * EMBED];
__device__ __align__(16) __half g_w16 [(size_t)MTOT * EMBED];
__device__ __align__(16) __half g_Wk16[EMBED * EMBED];
__device__ __align__(16) __half g_Wo16[EMBED * EMBED];

// ---------------------------------------------------------------------------
// Helpers
// ---------------------------------------------------------------------------
__device__ __forceinline__ uint32_t cvta_smem(const void* p) {
    uint32_t a;
    asm("{ .reg .u64 t; cvta.to.shared.u64 t, %1; cvt.u32.u64 %0, t; }"
        : "=r"(a) : "l"(p));
    return a;
}
__device__ __forceinline__ uint32_t sw128(uint32_t off) {
    return off ^ ((off >> 3) & 0x70);
}
__device__ __forceinline__ void ldsm4(uint32_t r[4], uint32_t a) {
    asm volatile("ldmatrix.sync.aligned.m8n8.x4.shared.b16 {%0,%1,%2,%3}, [%4];"
                 : "=r"(r[0]), "=r"(r[1]), "=r"(r[2]), "=r"(r[3]) : "r"(a));
}
__device__ __forceinline__ void ldsm4t(uint32_t r[4], uint32_t a) {
    asm volatile("ldmatrix.sync.aligned.m8n8.x4.trans.shared.b16 {%0,%1,%2,%3}, [%4];"
                 : "=r"(r[0]), "=r"(r[1]), "=r"(r[2]), "=r"(r[3]) : "r"(a));
}
__device__ __forceinline__ void mma16816h(float c[4], const uint32_t a[4],
                                          const uint32_t b[2]) {
    asm volatile(
        "mma.sync.aligned.m16n8k16.row.col.f32.f16.f16.f32 "
        "{%0,%1,%2,%3}, {%4,%5,%6,%7}, {%8,%9}, {%0,%1,%2,%3};"
        : "+f"(c[0]), "+f"(c[1]), "+f"(c[2]), "+f"(c[3])
        : "r"(a[0]), "r"(a[1]), "r"(a[2]), "r"(a[3]), "r"(b[0]), "r"(b[1]));
}
__device__ __forceinline__ uint32_t packh2(float lo, float hi) {
    uint32_t r;
    asm("cvt.rn.f16x2.f32 %0, %1, %2;" : "=r"(r) : "f"(hi), "f"(lo));
    return r;
}
__device__ __forceinline__ uint32_t ex2h2(uint32_t x) {
    uint32_t r;
    asm("ex2.approx.f16x2 %0, %1;" : "=r"(r) : "r"(x));
    return r;
}
__device__ __forceinline__ void cp16(uint32_t dst, const void* src) {
    asm volatile("cp.async.cg.shared.global [%0], [%1], 16;"
                 :: "r"(dst), "l"(src) : "memory");
}
__device__ __forceinline__ void cp_commit() {
    asm volatile("cp.async.commit_group;" ::: "memory");
}
template <int N>
__device__ __forceinline__ void cp_wait() {
    asm volatile("cp.async.wait_group %0;" :: "n"(N) : "memory");
}

// ---------------------------------------------------------------------------
// fp32 -> fp16 convert for ALL three tensors in ONE launch (linear range).
// ---------------------------------------------------------------------------
__global__ void to_f16_all(const float4* __restrict__ x,  uint32_t* __restrict__ ox,
                           const float4* __restrict__ wk, uint32_t* __restrict__ owk,
                           const float4* __restrict__ wo, uint32_t* __restrict__ owo,
                           int nX4, int nW4) {
    int i = blockIdx.x * blockDim.x + threadIdx.x;
    const float4* in;
    uint32_t* out;
    int j;
    if (i < nX4)                  { in = x;  out = ox;  j = i; }
    else if (i < nX4 + nW4)       { in = wk; out = owk; j = i - nX4; }
    else if (i < nX4 + 2 * nW4)   { in = wo; out = owo; j = i - nX4 - nW4; }
    else return;
    float4 v = in[j];
    out[2 * j]     = packh2(v.x, v.y);
    out[2 * j + 1] = packh2(v.z, v.w);
}

// ---------------------------------------------------------------------------
// Tensor-core GEMM, fp16 single product.
// R17: CTA tile 64x64, 4 warps (warp tile 32x32), 2-stage cp.async,
// __launch_bounds__(128, 6) -> 6 CTAs/SM (RF was the occupancy cap at 128
// regs; 32 accums -> ~75 regs).  Grid 1536/888 slots = 1.73 waves (86%
// utilization ceiling vs 65% before).  Per-accumulator MMA order unchanged
// -> bit-identical results.
// Stage (16384 B): A 8K | W 8K.
// ---------------------------------------------------------------------------
#define GSTG   16384
#define NCHUNK (EMBED / 64)

template <int OUT_F16>
__global__ void __launch_bounds__(128, 6) gemm_tc(
    const __half* __restrict__ A, const __half* __restrict__ W,
    const float* __restrict__ bias, float* __restrict__ Cf,
    __half* __restrict__ C16) {
    extern __shared__ __align__(1024) char smb[];
    const int tid = threadIdx.x;
    const int wid = tid >> 5, lane = tid & 31;
    const int wm = wid & 1, wn = wid >> 1;
    const int g = lane >> 2, q = lane & 3;
    const int sub = lane & 7, sel = lane >> 3;
    const int bm = blockIdx.y * 64, bn = blockIdx.x * 64;
    const uint32_t sb = cvta_smem(smb);

    auto prefetch = [&](int ch, int st) {
        const uint32_t dst = sb + st * GSTG;
        const int k0 = ch * 64;
        #pragma unroll
        for (int p = 0; p < 4; p++) {
            int idx = tid + p * 128;
            int r = idx >> 3, c8 = idx & 7;
            uint32_t off = sw128(r * 128 + c8 * 16);
            cp16(dst + off,        A + (size_t)(bm + r) * EMBED + k0 + c8 * 8);
            cp16(dst + 8192 + off, W + (size_t)(bn + r) * EMBED + k0 + c8 * 8);
        }
        cp_commit();
    };

    float c[2][4][4] = {};

    prefetch(0, 0);
    for (int ch = 0; ch < NCHUNK; ch++) {
        if (ch > 0) __syncthreads();
        if (ch + 1 < NCHUNK) { prefetch(ch + 1, (ch + 1) & 1); cp_wait<1>(); }
        else                 { cp_wait<0>(); }
        __syncthreads();
        const uint32_t base = sb + (ch & 1) * GSTG;

        #pragma unroll
        for (int ks = 0; ks < 4; ks++) {
            uint32_t ah[2][4];
            #pragma unroll
            for (int mi = 0; mi < 2; mi++) {
                int row = wm * 32 + mi * 16 + sub + (sel & 1) * 8;
                int colb = ks * 32 + (sel >> 1) * 16;
                ldsm4(ah[mi], base + sw128(row * 128 + colb));
            }
            uint32_t bh[2][4];
            #pragma unroll
            for (int nf2 = 0; nf2 < 2; nf2++) {
                int row = wn * 32 + nf2 * 16 + sub + (sel >> 1) * 8;
                int colb = ks * 32 + (sel & 1) * 16;
                ldsm4(bh[nf2], base + 8192 + sw128(row * 128 + colb));
            }
            #pragma unroll
            for (int mi = 0; mi < 2; mi++)
                #pragma unroll
                for (int nf = 0; nf < 4; nf++)
                    mma16816h(c[mi][nf], ah[mi], &bh[nf >> 1][(nf & 1) * 2]);
        }
    }

    #pragma unroll
    for (int mi = 0; mi < 2; mi++) {
        int r0 = bm + wm * 32 + mi * 16 + g;
        #pragma unroll
        for (int nf = 0; nf < 4; nf++) {
            int col = bn + wn * 32 + nf * 8 + q * 2;
            float b0 = bias[col], b1 = bias[col + 1];
            float v00 = c[mi][nf][0] + b0, v01 = c[mi][nf][1] + b1;
            float v10 = c[mi][nf][2] + b0, v11 = c[mi][nf][3] + b1;
            size_t o0 = (size_t)r0 * EMBED + col;
            size_t o1 = (size_t)(r0 + 8) * EMBED + col;
            if (OUT_F16) {
                *(uint32_t*)(C16 + o0) = packh2(v00, v01);
                *(uint32_t*)(C16 + o1) = packh2(v10, v11);
            } else {
                *(float2*)(Cf + o0) = make_float2(v00, v01);
                *(float2*)(Cf + o1) = make_float2(v10, v11);
            }
        }
    }
}

// ---------------------------------------------------------------------------
// Tensor-core flash attention — R13/R14 structure, FROZEN (74.5 us proven).
// ---------------------------------------------------------------------------
#define ASTG   8192
#define NJT    (SEQ / 64)

__global__ void __launch_bounds__(256, 2) attn_tc(
    const int* __restrict__ mask,
    const __half* __restrict__ K16,
    __half* __restrict__ O16) {
    extern __shared__ __align__(1024) char smb[];
    const int tid = threadIdx.x, wid = tid >> 5, lane = tid & 31;
    const int g = lane >> 2, q = lane & 3;
    const int sub = lane & 7, sel = lane >> 3;
    const int bh = blockIdx.y, b = bh / NHEADS, h = bh % NHEADS;
    const int i0 = blockIdx.x * 128;
    const uint32_t sb = cvta_smem(smb);
    const float Cs = 0.052058761f;  // log2(e)/sqrt(768)

    const size_t headoff = (size_t)b * SEQ * EMBED + h * HDIM;

    #pragma unroll
    for (int p = 0; p < 4; p++) {
        int idx = tid + p * 256;
        int r = idx >> 3, c8 = idx & 7;
        uint32_t off = sw128(r * 128 + c8 * 16);
        *(uint4*)(smb + off) =
            *(const uint4*)(K16 + headoff + (size_t)(i0 + r) * EMBED + c8 * 8);
    }
    __syncthreads();
    uint32_t q16[4][4];
    {
        const uint32_t C2 = packh2(Cs, Cs);
        #pragma unroll
        for (int ks = 0; ks < 4; ks++) {
            int row = wid * 16 + sub + (sel & 1) * 8;
            int colb = ks * 32 + (sel >> 1) * 16;
            ldsm4(q16[ks], sb + sw128(row * 128 + colb));
            #pragma unroll
            for (int i = 0; i < 4; i++)
                asm("mul.f16x2 %0, %0, %1;" : "+r"(q16[ks][i]) : "r"(C2));
        }
    }
    __syncthreads();

    auto prefetch = [&](int jt, int st) {
        const uint32_t dst = sb + st * ASTG;
        const int j0 = jt * 64;
        #pragma unroll
        for (int p = 0; p < 2; p++) {
            int idx = tid + p * 256;
            int r = idx >> 3, c8 = idx & 7;
            uint32_t off = sw128(r * 128 + c8 * 16);
            cp16(dst + off, K16 + headoff + (size_t)(j0 + r) * EMBED + c8 * 8);
        }
        cp_commit();
    };

    const int mrow = i0 + wid * 16 + g;
    const int mv0 = mask[b * SEQ + mrow];
    const int mv1 = mask[b * SEQ + mrow + 8];
    const uint32_t ones2[2] = {0x3C003C00u, 0x3C003C00u};  // f16x2 {1,1}

    float lc[4] = {};
    float o[8][4] = {};

    prefetch(0, 0);
    prefetch(1, 1);
    prefetch(2, 2);
    for (int jt = 0; jt < NJT; jt++) {
        if (jt > 0) __syncthreads();
        if (jt + 3 < NJT) prefetch(jt + 3, (jt + 3) & 3);
        if      (jt + 3 < NJT) cp_wait<3>();
        else if (jt + 2 < NJT) cp_wait<2>();
        else if (jt + 1 < NJT) cp_wait<1>();
        else                   cp_wait<0>();
        __syncthreads();
        const uint32_t base = sb + (jt & 3) * ASTG;

        float s[8][4] = {};
        #pragma unroll
        for (int ks = 0; ks < 4; ks++) {
            #pragma unroll
            for (int nf2 = 0; nf2 < 4; nf2++) {
                uint32_t bhr[4];
                int row = nf2 * 16 + sub + (sel >> 1) * 8;
                int colb = ks * 32 + (sel & 1) * 16;
                ldsm4(bhr, base + sw128(row * 128 + colb));
                mma16816h(s[nf2 * 2],     q16[ks], &bhr[0]);
                mma16816h(s[nf2 * 2 + 1], q16[ks], &bhr[2]);
            }
        }

        #pragma unroll
        for (int kj = 0; kj < 4; kj++) {
            uint32_t ph[4];
            {
                const float* s0 = s[2 * kj];
                const float* s1 = s[2 * kj + 1];
                ph[0] = mv0 ? packh2(s0[0], s0[1]) : 0u;
                ph[1] = mv1 ? packh2(s0[2], s0[3]) : 0u;
                ph[2] = mv0 ? packh2(s1[0], s1[1]) : 0u;
                ph[3] = mv1 ? packh2(s1[2], s1[3]) : 0u;
                ph[0] = ex2h2(ph[0]);
                ph[1] = ex2h2(ph[1]);
                ph[2] = ex2h2(ph[2]);
                ph[3] = ex2h2(ph[3]);
            }
            mma16816h(lc, ph, ones2);
            #pragma unroll
            for (int nd2 = 0; nd2 < 4; nd2++) {
                uint32_t vh[4];
                int row = kj * 16 + sub + (sel & 1) * 8;
                int colb = nd2 * 32 + (sel >> 1) * 16;
                ldsm4t(vh, base + sw128(row * 128 + colb));
                mma16816h(o[nd2 * 2],     ph, &vh[0]);
                mma16816h(o[nd2 * 2 + 1], ph, &vh[2]);
            }
        }
    }

    float inv0 = 1.f / lc[0], inv1 = 1.f / lc[2];
    const size_t r0 = (size_t)(b * SEQ + i0 + wid * 16 + g);
    #pragma unroll
    for (int nf = 0; nf < 8; nf++) {
        int col = h * HDIM + nf * 8 + q * 2;
        size_t o0 = r0 * EMBED + col, o1 = (r0 + 8) * EMBED + col;
        *(uint32_t*)(O16 + o0) = packh2(o[nf][0] * inv0, o[nf][1] * inv0);
        *(uint32_t*)(O16 + o1) = packh2(o[nf][2] * inv1, o[nf][3] * inv1);
    }
}

// ---------------------------------------------------------------------------
extern "C" void kernel_launch(void* const* d_in, const int* in_sizes, int n_in,
                              void* d_out, int out_size) {
    // Input order: x, attention_mask, Wq, bq, Wk, bk, Wv, bv, Wo, bo
    const float* x    = (const float*)d_in[0];
    const int*   mask = (const int*)  d_in[1];
    const float* Wk   = (const float*)d_in[4];
    const float* bk   = (const float*)d_in[5];
    const float* Wo   = (const float*)d_in[8];
    const float* bo   = (const float*)d_in[9];
    float*       out  = (float*)d_out;

    __half *x16, *K16, *w16, *Wk16, *Wo16;
    cudaGetSymbolAddress((void**)&x16,  g_x16);
    cudaGetSymbolAddress((void**)&K16,  g_K16);
    cudaGetSymbolAddress((void**)&w16,  g_w16);
    cudaGetSymbolAddress((void**)&Wk16, g_Wk16);
    cudaGetSymbolAddress((void**)&Wo16, g_Wo16);

    const int nX4 = MTOT * EMBED / 4;
    const int nW4 = EMBED * EMBED / 4;
    const int gsm  = 2 * GSTG;   // 32768
    const int asm_ = 4 * ASTG;   // 32768

    cudaFuncSetAttribute(gemm_tc<1>,
                         cudaFuncAttributeMaxDynamicSharedMemorySize, gsm);
    cudaFuncSetAttribute(gemm_tc<0>,
                         cudaFuncAttributeMaxDynamicSharedMemorySize, gsm);
    cudaFuncSetAttribute(attn_tc,
                         cudaFuncAttributeMaxDynamicSharedMemorySize, asm_);

    // one launch: x, Wk, Wo -> fp16
    const int ntot = nX4 + 2 * nW4;
    to_f16_all<<<(ntot + 255) / 256, 256>>>(
        (const float4*)x,  (uint32_t*)x16,
        (const float4*)Wk, (uint32_t*)Wk16,
        (const float4*)Wo, (uint32_t*)Wo16, nX4, nW4);

    // K = x @ Wk^T + bk  -> K16 (fp16)
    gemm_tc<1><<<dim3(EMBED / 64, MTOT / 64), 128, gsm>>>(
        x16, Wk16, bk, nullptr, K16);

    // fused masked self-attention (Q = K = V = K16) -> w16
    attn_tc<<<dim3(SEQ / 128, BATCH * NHEADS), 256, asm_>>>(mask, K16, w16);

    // out = w @ Wo^T + bo  (f32)
    gemm_tc<0><<<dim3(EMBED / 64, MTOT / 64), 128, gsm>>>(
        w16, Wo16, bo, out, nullptr);
}